// round 17
// baseline (speedup 1.0000x reference)
#include <cuda_runtime.h>
#include <math.h>

#define NMAX   50000
#define EMAX   800000
#define ETMAX  (EMAX + NMAX)
#define IN_C   128
#define HID    16
#define HEADS  8
#define H1C    (HEADS * HID)   // 128
#define OUT_C  64
#define NEG    0.2f
#define CSRB   64              // CSR blocks fused ahead of gemm1 blocks

// ---------------- scratch (device globals; no allocation allowed) ----------
__device__ float g_H1[(size_t)NMAX * H1C];     // layer1 projected features
__device__ float g_OUT1[(size_t)NMAX * H1C];   // layer1 output (post relu)
__device__ float g_H2[(size_t)NMAX * OUT_C];   // layer2 projected features
__device__ float g_al1s[NMAX * HEADS];
__device__ float g_al1d[NMAX * HEADS];
__device__ float g_al2s[NMAX];
__device__ float g_al2d[NMAX];
__device__ int   g_rowptr[NMAX + 1];
__device__ int   g_cnt[NMAX];                  // counts, then write cursors
__device__ int   g_esrc[ETMAX];                // src node per (dst-sorted) edge
__device__ int   g_bar;                        // CSR spin barrier (memset to 0)

// ---------------- CSR barrier (among the CSRB co-resident blocks) ----------
__device__ __forceinline__ void csr_barrier(int target) {
    __threadfence();
    __syncthreads();
    if (threadIdx.x == 0) {
        atomicAdd(&g_bar, 1);
        while (*(volatile int*)&g_bar < target) { }
        __threadfence();
    }
    __syncthreads();
}

// ---------------- fused: CSR build (blocks [0,CSRB)) | gemm1 (rest) --------
__global__ __launch_bounds__(512, 2) void gemm1_csr_kernel(
        const float* __restrict__ X, const float* __restrict__ W,
        const float* __restrict__ a1s, const float* __restrict__ a1d,
        const int* __restrict__ ei, int E, int ET, int M) {
    if (blockIdx.x < CSRB) {
        int tid = threadIdx.x;
        // phase 1: count degrees (g_cnt zeroed by host memset)
        for (int i = blockIdx.x * 512 + tid; i < ET; i += CSRB * 512) {
            int dst = (i < E) ? ei[E + i] : (i - E);   // self loops appended
            atomicAdd(&g_cnt[dst], 1);
        }
        csr_barrier(CSRB);
        // phase 2: exclusive scan (block 0 only)
        if (blockIdx.x == 0) {
            __shared__ int wsum[16];
            int lane = tid & 31, wid = tid >> 5;
            int C = (M + 511) / 512;
            int beg = tid * C;
            int end = beg + C; if (end > M) end = M;
            int sum = 0;
            for (int i = beg; i < end; i++) sum += g_cnt[i];
            int incl = sum;
#pragma unroll
            for (int off = 1; off < 32; off <<= 1) {
                int v = __shfl_up_sync(0xffffffffu, incl, off);
                if (lane >= off) incl += v;
            }
            if (lane == 31) wsum[wid] = incl;
            __syncthreads();
            if (wid == 0) {
                int w = (lane < 16) ? wsum[lane] : 0;
                int wi = w;
#pragma unroll
                for (int off = 1; off < 16; off <<= 1) {
                    int v = __shfl_up_sync(0xffffffffu, wi, off);
                    if (lane >= off) wi += v;
                }
                if (lane < 16) wsum[lane] = wi - w;   // exclusive warp base
            }
            __syncthreads();
            int run = wsum[wid] + (incl - sum);
            for (int i = beg; i < end; i++) {
                int c = g_cnt[i];
                g_rowptr[i] = run;
                g_cnt[i]    = run;
                run += c;
            }
            if (beg < M && end == M) g_rowptr[M] = run;
        }
        csr_barrier(2 * CSRB);
        // phase 3: scatter into dst-sorted edge list
        for (int i = blockIdx.x * 512 + tid; i < ET; i += CSRB * 512) {
            int src, dst;
            if (i < E) { src = ei[i]; dst = ei[E + i]; }
            else       { src = i - E; dst = i - E; }
            int pos = atomicAdd(&g_cnt[dst], 1);
            g_esrc[pos] = src;
        }
        return;
    }
    extern __shared__ float smem[];
    float4* Wsh = (float4*)smem;           // 128 * 32 float4 = 64 KB
    float*  Xsh = smem + 128 * 128;        // 64 * 128 floats = 32 KB
    int tid = threadIdx.x;

    const float4* W4 = (const float4*)W;
    for (int i = tid; i < 128 * 32; i += 512) Wsh[i] = W4[i];

    int row0 = (blockIdx.x - CSRB) * 64;
    for (int i = tid; i < 64 * 32; i += 512) {
        int r = i >> 5, kc = i & 31;
        float4 v = make_float4(0.f, 0.f, 0.f, 0.f);
        if (row0 + r < M) v = ((const float4*)X)[(size_t)(row0 + r) * 32 + kc];
        *(float4*)&Xsh[r * 128 + kc * 4] = v;
    }
    __syncthreads();

    int tx = tid & 31, ty = tid >> 5;      // warp == ty
    float4 acc[4];
#pragma unroll
    for (int r = 0; r < 4; r++) acc[r] = make_float4(0.f, 0.f, 0.f, 0.f);

    for (int k4 = 0; k4 < 32; k4++) {
        float4 wv0 = Wsh[(k4 * 4 + 0) * 32 + tx];
        float4 wv1 = Wsh[(k4 * 4 + 1) * 32 + tx];
        float4 wv2 = Wsh[(k4 * 4 + 2) * 32 + tx];
        float4 wv3 = Wsh[(k4 * 4 + 3) * 32 + tx];
#pragma unroll
        for (int r = 0; r < 4; r++) {
            float4 xv = *(const float4*)&Xsh[(ty * 4 + r) * 128 + k4 * 4];
            acc[r].x += xv.x * wv0.x + xv.y * wv1.x + xv.z * wv2.x + xv.w * wv3.x;
            acc[r].y += xv.x * wv0.y + xv.y * wv1.y + xv.z * wv2.y + xv.w * wv3.y;
            acc[r].z += xv.x * wv0.z + xv.y * wv1.z + xv.z * wv2.z + xv.w * wv3.z;
            acc[r].w += xv.x * wv0.w + xv.y * wv1.w + xv.z * wv2.w + xv.w * wv3.w;
        }
    }

    float4 as = ((const float4*)a1s)[tx];
    float4 ad = ((const float4*)a1d)[tx];
    int head = tx >> 2;
#pragma unroll
    for (int r = 0; r < 4; r++) {
        int row = row0 + ty * 4 + r;
        if (row < M) {
            ((float4*)g_H1)[(size_t)row * 32 + tx] = acc[r];
            float ps = acc[r].x * as.x + acc[r].y * as.y + acc[r].z * as.z + acc[r].w * as.w;
            float pd = acc[r].x * ad.x + acc[r].y * ad.y + acc[r].z * ad.z + acc[r].w * ad.w;
            ps += __shfl_xor_sync(0xffffffffu, ps, 1);
            ps += __shfl_xor_sync(0xffffffffu, ps, 2);
            pd += __shfl_xor_sync(0xffffffffu, pd, 1);
            pd += __shfl_xor_sync(0xffffffffu, pd, 2);
            if ((tx & 3) == 0) {
                g_al1s[row * 8 + head] = ps;
                g_al1d[row * 8 + head] = pd;
            }
        }
    }
}

// ---------------- GEMM2: H2 = OUT1 @ W2, fused al2 logits ------------------
__global__ __launch_bounds__(512, 2) void gemm2_kernel(
        const float* __restrict__ X, const float* __restrict__ W,
        const float* __restrict__ a2s, const float* __restrict__ a2d, int M) {
    extern __shared__ float smem[];
    float4* Wsh = (float4*)smem;           // 128 * 16 float4 = 32 KB
    float*  Xsh = smem + 128 * 64;         // 128 * 128 floats = 64 KB
    int tid = threadIdx.x;

    const float4* W4 = (const float4*)W;
    for (int i = tid; i < 128 * 16; i += 512) Wsh[i] = W4[i];

    int row0 = blockIdx.x * 128;
    for (int i = tid; i < 128 * 32; i += 512) {
        int r = i >> 5, kc = i & 31;
        float4 v = make_float4(0.f, 0.f, 0.f, 0.f);
        if (row0 + r < M) v = ((const float4*)X)[(size_t)(row0 + r) * 32 + kc];
        *(float4*)&Xsh[r * 128 + kc * 4] = v;
    }
    __syncthreads();

    int tx = tid & 15, ty = tid >> 4;      // 32 row-groups, 4 rows each
    float4 acc[4];
#pragma unroll
    for (int r = 0; r < 4; r++) acc[r] = make_float4(0.f, 0.f, 0.f, 0.f);

    for (int k4 = 0; k4 < 32; k4++) {
        float4 wv0 = Wsh[(k4 * 4 + 0) * 16 + tx];
        float4 wv1 = Wsh[(k4 * 4 + 1) * 16 + tx];
        float4 wv2 = Wsh[(k4 * 4 + 2) * 16 + tx];
        float4 wv3 = Wsh[(k4 * 4 + 3) * 16 + tx];
#pragma unroll
        for (int r = 0; r < 4; r++) {
            float4 xv = *(const float4*)&Xsh[(ty * 4 + r) * 128 + k4 * 4];
            acc[r].x += xv.x * wv0.x + xv.y * wv1.x + xv.z * wv2.x + xv.w * wv3.x;
            acc[r].y += xv.x * wv0.y + xv.y * wv1.y + xv.z * wv2.y + xv.w * wv3.y;
            acc[r].z += xv.x * wv0.z + xv.y * wv1.z + xv.z * wv2.z + xv.w * wv3.z;
            acc[r].w += xv.x * wv0.w + xv.y * wv1.w + xv.z * wv2.w + xv.w * wv3.w;
        }
    }

    float4 as = ((const float4*)a2s)[tx];
    float4 ad = ((const float4*)a2d)[tx];
#pragma unroll
    for (int r = 0; r < 4; r++) {
        int row = row0 + ty * 4 + r;
        if (row < M) {
            ((float4*)g_H2)[(size_t)row * 16 + tx] = acc[r];
            float ps = acc[r].x * as.x + acc[r].y * as.y + acc[r].z * as.z + acc[r].w * as.w;
            float pd = acc[r].x * ad.x + acc[r].y * ad.y + acc[r].z * ad.z + acc[r].w * ad.w;
#pragma unroll
            for (int off = 8; off >= 1; off >>= 1) {   // reduce within 16-lane group
                ps += __shfl_xor_sync(0xffffffffu, ps, off);
                pd += __shfl_xor_sync(0xffffffffu, pd, off);
            }
            if (tx == 0) { g_al2s[row] = ps; g_al2d[row] = pd; }
        }
    }
}

// ---------------- agg1: half-warp dual-edge, shuffle-free inner loop -------
// Half 0 takes even edges, half 1 odd edges; lane covers 8 channels
// (2 x float4). Per-edge overhead (esrc, logit, exp, bookkeeping) amortizes
// over 2 edges per warp iteration. Cross-half merge once per node.
__global__ void agg1_kernel(const float* __restrict__ b1, int n) {
    int node = (blockIdx.x * blockDim.x + threadIdx.x) >> 5;
    int lane = threadIdx.x & 31;
    if (node >= n) return;
    int hl   = lane & 15;       // lane within half
    int half = lane >> 4;       // 0: even edges, 1: odd edges
    int beg = g_rowptr[node], end = g_rowptr[node + 1];
    int head = hl >> 1;         // 8 channels/lane -> head = hl/2
    float ald = g_al1d[node * 8 + head];

    float denom = 0.f;
    float4 acc0 = make_float4(0.f, 0.f, 0.f, 0.f);
    float4 acc1 = make_float4(0.f, 0.f, 0.f, 0.f);

    int iters = (end - beg + 1) >> 1;   // ceil(deg/2), warp-uniform
    int j = beg + half;
    for (int it = 0; it < iters; it++, j += 2) {
        int inb = (j < end);
        int s = inb ? g_esrc[j] : 0;
        const float4* row = (const float4*)&g_H1[(size_t)s * 128];
        float4 v0 = row[hl * 2];
        float4 v1 = row[hl * 2 + 1];
        float e = g_al1s[s * 8 + head] + ald;
        e = (e > 0.f) ? e : NEG * e;
        float ee = inb ? __expf(e) : 0.f;
        denom += ee;
        acc0.x += ee * v0.x; acc0.y += ee * v0.y;
        acc0.z += ee * v0.z; acc0.w += ee * v0.w;
        acc1.x += ee * v1.x; acc1.y += ee * v1.y;
        acc1.z += ee * v1.z; acc1.w += ee * v1.w;
    }

    // merge halves (once per node)
    acc0.x += __shfl_xor_sync(0xffffffffu, acc0.x, 16);
    acc0.y += __shfl_xor_sync(0xffffffffu, acc0.y, 16);
    acc0.z += __shfl_xor_sync(0xffffffffu, acc0.z, 16);
    acc0.w += __shfl_xor_sync(0xffffffffu, acc0.w, 16);
    acc1.x += __shfl_xor_sync(0xffffffffu, acc1.x, 16);
    acc1.y += __shfl_xor_sync(0xffffffffu, acc1.y, 16);
    acc1.z += __shfl_xor_sync(0xffffffffu, acc1.z, 16);
    acc1.w += __shfl_xor_sync(0xffffffffu, acc1.w, 16);
    denom  += __shfl_xor_sync(0xffffffffu, denom,  16);

    if (half == 0) {
        float inv = 1.f / (denom + 1e-16f);
        float4 bb0 = ((const float4*)b1)[hl * 2];
        float4 bb1 = ((const float4*)b1)[hl * 2 + 1];
        float4 o0, o1;
        o0.x = fmaxf(acc0.x * inv + bb0.x, 0.f);
        o0.y = fmaxf(acc0.y * inv + bb0.y, 0.f);
        o0.z = fmaxf(acc0.z * inv + bb0.z, 0.f);
        o0.w = fmaxf(acc0.w * inv + bb0.w, 0.f);
        o1.x = fmaxf(acc1.x * inv + bb1.x, 0.f);
        o1.y = fmaxf(acc1.y * inv + bb1.y, 0.f);
        o1.z = fmaxf(acc1.z * inv + bb1.z, 0.f);
        o1.w = fmaxf(acc1.w * inv + bb1.w, 0.f);
        ((float4*)g_OUT1)[(size_t)node * 32 + hl * 2]     = o0;
        ((float4*)g_OUT1)[(size_t)node * 32 + hl * 2 + 1] = o1;
    }
}

// ---------------- agg2: half-warp dual-edge --------------------------------
// Lane covers 4 channels (1 x float4); logit chain amortized over 2 edges.
__global__ void agg2_kernel(const float* __restrict__ b2,
                            float* __restrict__ out, int n) {
    int node = (blockIdx.x * blockDim.x + threadIdx.x) >> 5;
    int lane = threadIdx.x & 31;
    if (node >= n) return;
    int hl   = lane & 15;
    int half = lane >> 4;
    int beg = g_rowptr[node], end = g_rowptr[node + 1];
    float ald = g_al2d[node];

    float denom = 0.f;
    float4 acc = make_float4(0.f, 0.f, 0.f, 0.f);

    int iters = (end - beg + 1) >> 1;
    int j = beg + half;
    for (int it = 0; it < iters; it++, j += 2) {
        int inb = (j < end);
        int s = inb ? g_esrc[j] : 0;
        float4 v = ((const float4*)g_H2)[(size_t)s * 16 + hl];
        float e = g_al2s[s] + ald;
        e = (e > 0.f) ? e : NEG * e;
        float ee = inb ? __expf(e) : 0.f;
        denom += ee;
        acc.x += ee * v.x; acc.y += ee * v.y;
        acc.z += ee * v.z; acc.w += ee * v.w;
    }

    acc.x += __shfl_xor_sync(0xffffffffu, acc.x, 16);
    acc.y += __shfl_xor_sync(0xffffffffu, acc.y, 16);
    acc.z += __shfl_xor_sync(0xffffffffu, acc.z, 16);
    acc.w += __shfl_xor_sync(0xffffffffu, acc.w, 16);
    denom += __shfl_xor_sync(0xffffffffu, denom, 16);

    if (half == 0) {
        float inv = 1.f / (denom + 1e-16f);
        float4 b = ((const float4*)b2)[hl];
        ((float4*)out)[(size_t)node * 16 + hl] =
            make_float4(acc.x * inv + b.x, acc.y * inv + b.y,
                        acc.z * inv + b.z, acc.w * inv + b.w);
    }
}

// ---------------- launch ---------------------------------------------------
extern "C" void kernel_launch(void* const* d_in, const int* in_sizes, int n_in,
                              void* d_out, int out_size) {
    const float* x    = (const float*)d_in[0];
    const int*   ei   = (const int*)  d_in[1];
    const float* W1   = (const float*)d_in[2];
    const float* a1s  = (const float*)d_in[3];
    const float* a1d  = (const float*)d_in[4];
    const float* b1   = (const float*)d_in[5];
    const float* W2   = (const float*)d_in[6];
    const float* a2s  = (const float*)d_in[7];
    const float* a2d  = (const float*)d_in[8];
    const float* b2   = (const float*)d_in[9];
    float* out = (float*)d_out;

    int n  = in_sizes[0] / IN_C;
    int E  = in_sizes[1] / 2;
    int ET = E + n;

    float *pOUT1;
    int   *pCnt, *pBar;
    cudaGetSymbolAddress((void**)&pOUT1, g_OUT1);
    cudaGetSymbolAddress((void**)&pCnt,  g_cnt);
    cudaGetSymbolAddress((void**)&pBar,  g_bar);

    // zero counters (CSR build itself is fused into the gemm1 launch)
    cudaMemsetAsync(pCnt, 0, (size_t)n * sizeof(int));
    cudaMemsetAsync(pBar, 0, sizeof(int));

    // layer 1: fused CSR | gemm1
    const int SM1 = 128 * 128 * 4 + 64 * 128 * 4;  // 98304 B -> 2 blocks/SM
    cudaFuncSetAttribute((const void*)gemm1_csr_kernel,
                         cudaFuncAttributeMaxDynamicSharedMemorySize, SM1);
    int g1 = CSRB + (n + 63) / 64;
    gemm1_csr_kernel<<<g1, 512, SM1>>>(x, W1, a1s, a1d, ei, E, ET, n);
    agg1_kernel<<<(n + 7) / 8, 256>>>(b1, n);

    // layer 2
    const int SM2 = 128 * 64 * 4 + 128 * 128 * 4;  // 98304 B -> 2 blocks/SM
    cudaFuncSetAttribute((const void*)gemm2_kernel,
                         cudaFuncAttributeMaxDynamicSharedMemorySize, SM2);
    gemm2_kernel<<<(n + 127) / 128, 512, SM2>>>(pOUT1, W2, a2s, a2d, n);
    agg2_kernel<<<(n + 7) / 8, 256>>>(b2, out, n);
}